// round 1
// baseline (speedup 1.0000x reference)
#include <cuda_runtime.h>
#include <math.h>

// Problem constants (FP_Layer: B=8, N=8192, M=2048, C1=128, C2=256, H=256)
#define BB    8
#define NPTS  8192
#define MPTS  2048
#define C1    128
#define C2    256
#define HDIM  256
#define CIN   384
#define ROWS  (BB * NPTS)      // 65536
#define NPART 256              // partial-reduction blocks for BN stats

// ---------------- scratch (device globals; no allocation allowed) ----------
__device__ float g_interp[(size_t)ROWS * C2];   // 64 MB
__device__ float g_y1[(size_t)ROWS * HDIM];     // 64 MB
__device__ int   g_idx[ROWS * 3];
__device__ float g_w[ROWS * 3];
__device__ float g_psum[NPART * HDIM];
__device__ float g_psq[NPART * HDIM];
__device__ float g_a[HDIM];
__device__ float g_c[HDIM];

// ---------------- 1) 3-NN over xyz2 for every xyz1 point -------------------
// grid: BB * (NPTS/256) = 256 blocks, 256 threads. Whole xyz2[b] in smem.
__global__ void __launch_bounds__(256) knn_kernel(const float* __restrict__ xyz1,
                                                  const float* __restrict__ xyz2) {
    __shared__ float sx[MPTS], sy[MPTS], sz[MPTS], sn[MPTS];
    int b    = blockIdx.x >> 5;        // 32 tiles of 256 points per batch
    int tile = blockIdx.x & 31;
    const float* x2 = xyz2 + (size_t)b * MPTS * 3;
    for (int i = threadIdx.x; i < MPTS; i += 256) {
        float x = x2[i * 3 + 0], y = x2[i * 3 + 1], z = x2[i * 3 + 2];
        sx[i] = x; sy[i] = y; sz[i] = z;
        sn[i] = x * x + y * y + z * z;
    }
    __syncthreads();

    int n = tile * 256 + threadIdx.x;
    int r = b * NPTS + n;
    float px = xyz1[(size_t)r * 3 + 0];
    float py = xyz1[(size_t)r * 3 + 1];
    float pz = xyz1[(size_t)r * 3 + 2];
    float pn = px * px + py * py + pz * pz;

    float d0 = 3.4e38f, d1 = 3.4e38f, d2 = 3.4e38f;
    int   i0 = 0, i1 = 0, i2 = 0;
    #pragma unroll 4
    for (int m = 0; m < MPTS; m++) {
        // identical formula to reference: |a|^2 + |b|^2 - 2 a.b
        float d = (pn + sn[m]) - 2.f * (px * sx[m] + py * sy[m] + pz * sz[m]);
        if (d < d2) {
            if (d < d1) {
                d2 = d1; i2 = i1;
                if (d < d0) { d1 = d0; i1 = i0; d0 = d; i0 = m; }
                else        { d1 = d;  i1 = m; }
            } else { d2 = d; i2 = m; }
        }
    }
    float r0 = 1.f / (d0 + 1e-8f);
    float r1 = 1.f / (d1 + 1e-8f);
    float r2 = 1.f / (d2 + 1e-8f);
    float s  = (r0 + r1) + r2;
    g_idx[r * 3 + 0] = i0; g_idx[r * 3 + 1] = i1; g_idx[r * 3 + 2] = i2;
    g_w[r * 3 + 0] = r0 / s; g_w[r * 3 + 1] = r1 / s; g_w[r * 3 + 2] = r2 / s;
}

// ---------------- 2) weighted gather of points2 -> g_interp ----------------
// one warp per output point; lanes stride over 256 channels
__global__ void __launch_bounds__(256) interp_kernel(const float* __restrict__ points2) {
    int warp = (blockIdx.x * 256 + threadIdx.x) >> 5;
    int lane = threadIdx.x & 31;
    if (warp >= ROWS) return;
    int b = warp / NPTS;
    const float* p2 = points2 + (size_t)b * MPTS * C2;
    int   i0 = g_idx[warp * 3 + 0], i1 = g_idx[warp * 3 + 1], i2 = g_idx[warp * 3 + 2];
    float w0 = g_w[warp * 3 + 0],  w1 = g_w[warp * 3 + 1],  w2 = g_w[warp * 3 + 2];
    const float* q0 = p2 + (size_t)i0 * C2;
    const float* q1 = p2 + (size_t)i1 * C2;
    const float* q2 = p2 + (size_t)i2 * C2;
    float* o = g_interp + (size_t)warp * C2;
    #pragma unroll
    for (int c = lane; c < C2; c += 32)
        o[c] = (q0[c] * w0 + q1[c] * w1) + q2[c] * w2;
}

// ---------------- 3) tiled fp32 GEMM  C = A * W^T + bias -------------------
// MODE 0: A = [points1 | g_interp] (K=384), writes g_y1
// MODE 1: A = relu(bn(g_y1)) via g_a/g_c (K=256), writes Cout (d_out)
// block tile 128x128, thread tile 8x8, BK=8, 256 threads
template <int MODE>
__global__ void __launch_bounds__(256) gemm_kernel(const float* __restrict__ A0,
                                                   const float* __restrict__ Wm,
                                                   const float* __restrict__ bias,
                                                   float* __restrict__ Cout) {
    constexpr int K = (MODE == 0) ? CIN : HDIM;
    __shared__ float As[8][132];
    __shared__ float Bs[8][132];
    __shared__ float sA[HDIM], sC[HDIM];

    int tid = threadIdx.x;
    if (MODE == 1) { sA[tid] = g_a[tid]; sC[tid] = g_c[tid]; }
    __syncthreads();

    int rowBase = blockIdx.y * 128;
    int colBase = blockIdx.x * 128;
    int arow = tid >> 1;             // 0..127
    int ak   = (tid & 1) << 2;       // 0 or 4
    int row  = rowBase + arow;
    int ncol = colBase + arow;
    int tx = tid & 15, ty = tid >> 4;

    float acc[8][8];
    #pragma unroll
    for (int i = 0; i < 8; i++)
        #pragma unroll
        for (int j = 0; j < 8; j++) acc[i][j] = 0.f;

    for (int kt = 0; kt < K; kt += 8) {
        int gk = kt + ak;
        float4 av;
        if (MODE == 0) {
            if (gk < C1) av = *(const float4*)(A0 + (size_t)row * C1 + gk);
            else         av = *(const float4*)(g_interp + (size_t)row * C2 + (gk - C1));
        } else {
            av = *(const float4*)(g_y1 + (size_t)row * HDIM + gk);
            av.x = fmaxf(av.x * sA[gk + 0] + sC[gk + 0], 0.f);
            av.y = fmaxf(av.y * sA[gk + 1] + sC[gk + 1], 0.f);
            av.z = fmaxf(av.z * sA[gk + 2] + sC[gk + 2], 0.f);
            av.w = fmaxf(av.w * sA[gk + 3] + sC[gk + 3], 0.f);
        }
        As[ak + 0][arow] = av.x; As[ak + 1][arow] = av.y;
        As[ak + 2][arow] = av.z; As[ak + 3][arow] = av.w;

        float4 wv = *(const float4*)(Wm + (size_t)ncol * K + gk);
        Bs[ak + 0][arow] = wv.x; Bs[ak + 1][arow] = wv.y;
        Bs[ak + 2][arow] = wv.z; Bs[ak + 3][arow] = wv.w;

        __syncthreads();
        #pragma unroll
        for (int k = 0; k < 8; k++) {
            float4 a0 = *(const float4*)&As[k][ty * 8];
            float4 a1 = *(const float4*)&As[k][ty * 8 + 4];
            float4 b0 = *(const float4*)&Bs[k][tx * 8];
            float4 b1 = *(const float4*)&Bs[k][tx * 8 + 4];
            float ar[8] = {a0.x, a0.y, a0.z, a0.w, a1.x, a1.y, a1.z, a1.w};
            float br[8] = {b0.x, b0.y, b0.z, b0.w, b1.x, b1.y, b1.z, b1.w};
            #pragma unroll
            for (int i = 0; i < 8; i++)
                #pragma unroll
                for (int j = 0; j < 8; j++)
                    acc[i][j] = fmaf(ar[i], br[j], acc[i][j]);
        }
        __syncthreads();
    }

    float bb[8];
    #pragma unroll
    for (int j = 0; j < 8; j++) bb[j] = bias[colBase + tx * 8 + j];
    float* dst = (MODE == 0) ? g_y1 : Cout;
    #pragma unroll
    for (int i = 0; i < 8; i++) {
        int r = rowBase + ty * 8 + i;
        float4 v0 = {acc[i][0] + bb[0], acc[i][1] + bb[1], acc[i][2] + bb[2], acc[i][3] + bb[3]};
        float4 v1 = {acc[i][4] + bb[4], acc[i][5] + bb[5], acc[i][6] + bb[6], acc[i][7] + bb[7]};
        *(float4*)(dst + (size_t)r * HDIM + colBase + tx * 8)     = v0;
        *(float4*)(dst + (size_t)r * HDIM + colBase + tx * 8 + 4) = v1;
    }
}

// ---------------- 4) BN statistics (deterministic 2-stage reduce) ----------
// SRC 0: read g_y1 ; SRC 1: read p_ext (d_out)
template <int SRC>
__global__ void __launch_bounds__(256) stats_part_kernel(const float* __restrict__ p_ext) {
    const float* y = (SRC == 0) ? (const float*)g_y1 : p_ext;
    int t = threadIdx.x;                           // channel
    const float* p = y + (size_t)blockIdx.x * (ROWS / NPART) * HDIM + t;
    float s = 0.f, s2 = 0.f;
    #pragma unroll 4
    for (int r = 0; r < ROWS / NPART; r++) {
        float v = p[(size_t)r * HDIM];
        s += v; s2 += v * v;
    }
    g_psum[blockIdx.x * HDIM + t] = s;
    g_psq[blockIdx.x * HDIM + t]  = s2;
}

__global__ void __launch_bounds__(256) stats_final_kernel(const float* __restrict__ gamma,
                                                          const float* __restrict__ beta) {
    int t = threadIdx.x;
    float s = 0.f, s2 = 0.f;
    for (int i = 0; i < NPART; i++) { s += g_psum[i * HDIM + t]; s2 += g_psq[i * HDIM + t]; }
    float mean = s * (1.f / (float)ROWS);
    float var  = s2 * (1.f / (float)ROWS) - mean * mean;
    float a    = gamma[t] * rsqrtf(var + 1e-5f);
    g_a[t] = a;
    g_c[t] = beta[t] - mean * a;
}

// ---------------- 5) in-place bn+relu on d_out ------------------------------
__global__ void __launch_bounds__(256) bnrelu_kernel(float* __restrict__ out) {
    size_t i = (size_t)blockIdx.x * 256 + threadIdx.x;   // float4 index
    float4* o4 = (float4*)out;
    float4 v = o4[i];
    int c = (int)((i << 2) & (HDIM - 1));
    v.x = fmaxf(v.x * g_a[c + 0] + g_c[c + 0], 0.f);
    v.y = fmaxf(v.y * g_a[c + 1] + g_c[c + 1], 0.f);
    v.z = fmaxf(v.z * g_a[c + 2] + g_c[c + 2], 0.f);
    v.w = fmaxf(v.w * g_a[c + 3] + g_c[c + 3], 0.f);
    o4[i] = v;
}

// ---------------- host ------------------------------------------------------
extern "C" void kernel_launch(void* const* d_in, const int* in_sizes, int n_in,
                              void* d_out, int out_size) {
    const float* xyz1    = (const float*)d_in[0];
    const float* xyz2    = (const float*)d_in[1];
    const float* points1 = (const float*)d_in[2];
    const float* points2 = (const float*)d_in[3];
    const float* W1      = (const float*)d_in[4];
    const float* b1      = (const float*)d_in[5];
    const float* gamma1  = (const float*)d_in[6];
    const float* beta1   = (const float*)d_in[7];
    const float* W2      = (const float*)d_in[8];
    const float* b2      = (const float*)d_in[9];
    const float* gamma2  = (const float*)d_in[10];
    const float* beta2   = (const float*)d_in[11];
    float* out = (float*)d_out;

    knn_kernel<<<BB * (NPTS / 256), 256>>>(xyz1, xyz2);
    interp_kernel<<<(ROWS * 32) / 256, 256>>>(points2);

    gemm_kernel<0><<<dim3(HDIM / 128, ROWS / 128), 256>>>(points1, W1, b1, nullptr);
    stats_part_kernel<0><<<NPART, 256>>>(nullptr);
    stats_final_kernel<<<1, 256>>>(gamma1, beta1);

    gemm_kernel<1><<<dim3(HDIM / 128, ROWS / 128), 256>>>(nullptr, W2, b2, out);
    stats_part_kernel<1><<<NPART, 256>>>(out);
    stats_final_kernel<<<1, 256>>>(gamma2, beta2);

    bnrelu_kernel<<<(ROWS * HDIM / 4) / 256, 256>>>(out);
}

// round 3
// speedup vs baseline: 1.9957x; 1.9957x over previous
#include <cuda_runtime.h>
#include <cuda_bf16.h>
#include <cstdint>
#include <math.h>

// Problem constants (FP_Layer: B=8, N=8192, M=2048, C1=128, C2=256, H=256)
#define BB    8
#define NPTS  8192
#define MPTS  2048
#define C1    128
#define C2    256
#define HDIM  256
#define CIN   384
#define ROWS  (BB * NPTS)      // 65536
#define NPART 512
#define KC    64               // K-chunk per stage

// ---------------- scratch (device globals; no allocation allowed) ----------
__device__ float g_y1[(size_t)ROWS * HDIM];     // 64 MB
__device__ int   g_idx[ROWS * 3];
__device__ float g_w[ROWS * 3];
__device__ float g_psum[NPART * HDIM];
__device__ float g_psq[NPART * HDIM];
__device__ float g_a[HDIM];
__device__ float g_c[HDIM];
// W split to bf16 hi/lo (prep kernel), row-major [out_ch][in_ch]
__device__ __align__(16) __nv_bfloat16 g_w1h[256 * 384];
__device__ __align__(16) __nv_bfloat16 g_w1l[256 * 384];
__device__ __align__(16) __nv_bfloat16 g_w2h[256 * 256];
__device__ __align__(16) __nv_bfloat16 g_w2l[256 * 256];

// ================= PTX helpers (baseline ISA: sm_80-era, OK on compute_103) =
__device__ __forceinline__ uint32_t smem_u32(const void* p) {
    uint32_t a;
    asm("{ .reg .u64 t; cvta.to.shared.u64 t, %1; cvt.u32.u64 %0, t; }" : "=r"(a) : "l"(p));
    return a;
}
__device__ __forceinline__ void cpa16(uint32_t s, const void* g) {
    asm volatile("cp.async.cg.shared.global [%0], [%1], 16;" :: "r"(s), "l"(g));
}
#define CP_COMMIT() asm volatile("cp.async.commit_group;" ::: "memory")
#define CP_WAIT1()  asm volatile("cp.async.wait_group 1;" ::: "memory")
#define CP_WAIT0()  asm volatile("cp.async.wait_group 0;" ::: "memory")

__device__ __forceinline__ void ldsm4(uint32_t* r, uint32_t addr) {
    asm volatile("ldmatrix.sync.aligned.m8n8.x4.shared.b16 {%0,%1,%2,%3}, [%4];"
                 : "=r"(r[0]), "=r"(r[1]), "=r"(r[2]), "=r"(r[3]) : "r"(addr));
}
__device__ __forceinline__ void mma_bf16(float* c, const uint32_t* a, const uint32_t* b) {
    asm volatile(
        "mma.sync.aligned.m16n8k16.row.col.f32.bf16.bf16.f32 "
        "{%0,%1,%2,%3}, {%4,%5,%6,%7}, {%8,%9}, {%0,%1,%2,%3};"
        : "+f"(c[0]), "+f"(c[1]), "+f"(c[2]), "+f"(c[3])
        : "r"(a[0]), "r"(a[1]), "r"(a[2]), "r"(a[3]), "r"(b[0]), "r"(b[1]));
}

// ---------------- 0) split W into bf16 hi/lo --------------------------------
__global__ void __launch_bounds__(256) prep_w_kernel(const float* __restrict__ W1,
                                                     const float* __restrict__ W2) {
    int i = blockIdx.x * 256 + threadIdx.x;   // grid covers 256*384
    {
        float v = W1[i];
        __nv_bfloat16 h = __float2bfloat16(v);
        g_w1h[i] = h;
        g_w1l[i] = __float2bfloat16(v - __bfloat162float(h));
    }
    if (i < 256 * 256) {
        float v = W2[i];
        __nv_bfloat16 h = __float2bfloat16(v);
        g_w2h[i] = h;
        g_w2l[i] = __float2bfloat16(v - __bfloat162float(h));
    }
}

// ---------------- 1) 3-NN over xyz2 for every xyz1 point -------------------
__global__ void __launch_bounds__(256) knn_kernel(const float* __restrict__ xyz1,
                                                  const float* __restrict__ xyz2) {
    __shared__ float sx[MPTS], sy[MPTS], sz[MPTS], sn[MPTS];
    int b    = blockIdx.x >> 5;
    int tile = blockIdx.x & 31;
    const float* x2 = xyz2 + (size_t)b * MPTS * 3;
    for (int i = threadIdx.x; i < MPTS; i += 256) {
        float x = x2[i * 3 + 0], y = x2[i * 3 + 1], z = x2[i * 3 + 2];
        sx[i] = x; sy[i] = y; sz[i] = z;
        sn[i] = x * x + y * y + z * z;
    }
    __syncthreads();

    int n = tile * 256 + threadIdx.x;
    int r = b * NPTS + n;
    float px = xyz1[(size_t)r * 3 + 0];
    float py = xyz1[(size_t)r * 3 + 1];
    float pz = xyz1[(size_t)r * 3 + 2];
    float pn = px * px + py * py + pz * pz;

    float d0 = 3.4e38f, d1 = 3.4e38f, d2 = 3.4e38f;
    int   i0 = 0, i1 = 0, i2 = 0;
    #pragma unroll 4
    for (int m = 0; m < MPTS; m++) {
        float d = (pn + sn[m]) - 2.f * (px * sx[m] + py * sy[m] + pz * sz[m]);
        if (d < d2) {
            if (d < d1) {
                d2 = d1; i2 = i1;
                if (d < d0) { d1 = d0; i1 = i0; d0 = d; i0 = m; }
                else        { d1 = d;  i1 = m; }
            } else { d2 = d; i2 = m; }
        }
    }
    float r0 = 1.f / (d0 + 1e-8f);
    float r1 = 1.f / (d1 + 1e-8f);
    float r2 = 1.f / (d2 + 1e-8f);
    float s  = (r0 + r1) + r2;
    g_idx[r * 3 + 0] = i0; g_idx[r * 3 + 1] = i1; g_idx[r * 3 + 2] = i2;
    g_w[r * 3 + 0] = r0 / s; g_w[r * 3 + 1] = r1 / s; g_w[r * 3 + 2] = r2 / s;
}

// ---------------- 2) split-bf16 HMMA GEMM  C = A * W^T + bias ---------------
// MODE 0: A = [points1 | interp(points2)] (K=384), writes g_y1
// MODE 1: A = relu(bn(g_y1))              (K=256), writes dst_
// CTA tile 64(M) x 256(N), 8 warps (warp tile 64x32), K-chunk 64, 2 stages.
// 3 passes in fp32 accum: Ah*Bh + Ah*Bl + Al*Bh  (rel err ~2^-17)
//
// smem (dynamic): bias 1KB | bn_a 1KB | bn_c 1KB | 2 stages:
//   stage: A_hi 64x72 bf16 (9216B) | A_lo (9216B) | B_hi 256x72 (36864B) | B_lo
#define PITCHB    144                     // 72 bf16 per row
#define OFF_BIAS  0
#define OFF_BNA   1024
#define OFF_BNC   2048
#define OFF_T     3072
#define STG_SZ    92160
#define OFF_AH(s) (OFF_T + (s) * STG_SZ)
#define OFF_AL(s) (OFF_AH(s) + 9216)
#define OFF_BH(s) (OFF_AH(s) + 18432)
#define OFF_BL(s) (OFF_AH(s) + 55296)
#define SMEM_SZ   (OFF_T + 2 * STG_SZ)    // 187392

template <int MODE>
__global__ void __launch_bounds__(256, 1) gemm_hmma(const float* __restrict__ A0,
                                                    const float* __restrict__ P2,
                                                    const float* __restrict__ bias,
                                                    float* __restrict__ dst_) {
    constexpr int K  = MODE ? HDIM : CIN;
    constexpr int NC = K / KC;
    extern __shared__ char smem[];
    const uint32_t sb = smem_u32(smem);
    const int tid = threadIdx.x, wid = tid >> 5, lane = tid & 31;
    const int rowBase = blockIdx.x * 64;

    const __nv_bfloat16* WH = MODE ? g_w2h : g_w1h;
    const __nv_bfloat16* WL = MODE ? g_w2l : g_w1l;

    float* sBias = (float*)(smem + OFF_BIAS);
    float* sBnA  = (float*)(smem + OFF_BNA);
    float* sBnC  = (float*)(smem + OFF_BNC);
    sBias[tid] = bias[tid];
    if (MODE == 1) { sBnA[tid] = g_a[tid]; sBnC[tid] = g_c[tid]; }
    __syncthreads();

    // ---- A-fill thread mapping: 4 threads per row, 16 k each
    const int ar = tid >> 2;          // 0..63  (tile row)
    const int aq = tid & 3;           // 0..3   (k quarter)
    const int gr = rowBase + ar;      // global row

    int i0 = 0, i1 = 0, i2 = 0;
    float w0 = 0.f, w1 = 0.f, w2 = 0.f;
    const float* p2b = nullptr;
    if (MODE == 0) {
        i0 = g_idx[gr * 3 + 0]; i1 = g_idx[gr * 3 + 1]; i2 = g_idx[gr * 3 + 2];
        w0 = g_w[gr * 3 + 0];  w1 = g_w[gr * 3 + 1];  w2 = g_w[gr * 3 + 2];
        p2b = P2 + (size_t)(gr >> 13) * MPTS * C2;     // gr / NPTS
    }

    // ================= fill helpers (inlined via lambdas) ==================
    auto fillB = [&](int c, int s) {
        const int kt = c * KC;
        #pragma unroll
        for (int it = 0; it < 8; it++) {
            const int idx = tid + 256 * it;       // 0..2047
            const int n = idx >> 3, j = idx & 7;  // row, 16B chunk
            const uint32_t soff = (uint32_t)(n * PITCHB + j * 16);
            const size_t goff = (size_t)n * K + kt + j * 8;
            cpa16(sb + OFF_BH(s) + soff, WH + goff);
            cpa16(sb + OFF_BL(s) + soff, WL + goff);
        }
    };
    auto fillA = [&](int c, int s) {
        const int kt = c * KC;
        float vals[16];
        if (MODE == 0) {
            if (kt < C1) {
                const float* src = A0 + (size_t)gr * C1 + kt + aq * 16;
                #pragma unroll
                for (int j = 0; j < 4; j++) {
                    float4 f = *(const float4*)(src + 4 * j);
                    vals[4 * j + 0] = f.x; vals[4 * j + 1] = f.y;
                    vals[4 * j + 2] = f.z; vals[4 * j + 3] = f.w;
                }
            } else {
                const int cc = kt - C1 + aq * 16;
                const float* q0 = p2b + (size_t)i0 * C2 + cc;
                const float* q1 = p2b + (size_t)i1 * C2 + cc;
                const float* q2 = p2b + (size_t)i2 * C2 + cc;
                #pragma unroll
                for (int j = 0; j < 4; j++) {
                    float4 a = *(const float4*)(q0 + 4 * j);
                    float4 b = *(const float4*)(q1 + 4 * j);
                    float4 d = *(const float4*)(q2 + 4 * j);
                    vals[4 * j + 0] = a.x * w0 + b.x * w1 + d.x * w2;
                    vals[4 * j + 1] = a.y * w0 + b.y * w1 + d.y * w2;
                    vals[4 * j + 2] = a.z * w0 + b.z * w1 + d.z * w2;
                    vals[4 * j + 3] = a.w * w0 + b.w * w1 + d.w * w2;
                }
            }
        } else {
            const int kb = kt + aq * 16;
            const float* src = g_y1 + (size_t)gr * HDIM + kb;
            #pragma unroll
            for (int j = 0; j < 4; j++) {
                float4 f = *(const float4*)(src + 4 * j);
                const int g = kb + 4 * j;
                vals[4 * j + 0] = fmaxf(f.x * sBnA[g + 0] + sBnC[g + 0], 0.f);
                vals[4 * j + 1] = fmaxf(f.y * sBnA[g + 1] + sBnC[g + 1], 0.f);
                vals[4 * j + 2] = fmaxf(f.z * sBnA[g + 2] + sBnC[g + 2], 0.f);
                vals[4 * j + 3] = fmaxf(f.w * sBnA[g + 3] + sBnC[g + 3], 0.f);
            }
        }
        #pragma unroll
        for (int j = 0; j < 8; j++) {
            const float x = vals[2 * j], y = vals[2 * j + 1];
            __nv_bfloat162 h, l;
            h.x = __float2bfloat16(x);
            h.y = __float2bfloat16(y);
            l.x = __float2bfloat16(x - __bfloat162float(h.x));
            l.y = __float2bfloat16(y - __bfloat162float(h.y));
            const uint32_t boff = (uint32_t)(ar * PITCHB + (aq * 16 + 2 * j) * 2);
            *(__nv_bfloat162*)(smem + OFF_AH(0) + (size_t)s * STG_SZ + boff) = h;
            *(__nv_bfloat162*)(smem + OFF_AL(0) + (size_t)s * STG_SZ + boff) = l;
        }
    };

    // ---- accumulators init = bias (folded epilogue add)
    const int nb = wid * 32;
    float acc[4][4][4];
    #pragma unroll
    for (int nt = 0; nt < 4; nt++) {
        const float b0 = sBias[nb + nt * 8 + 2 * (lane & 3)];
        const float b1 = sBias[nb + nt * 8 + 2 * (lane & 3) + 1];
        #pragma unroll
        for (int mt = 0; mt < 4; mt++) {
            acc[mt][nt][0] = b0; acc[mt][nt][1] = b1;
            acc[mt][nt][2] = b0; acc[mt][nt][3] = b1;
        }
    }

    // ldmatrix per-lane address parts
    const uint32_t aRow = (uint32_t)(((lane >> 3) & 1) * 8 + (lane & 7));
    const uint32_t aK   = (uint32_t)((lane >> 4) * 8);
    const uint32_t bRow = (uint32_t)((lane >> 4) * 8 + (lane & 7));
    const uint32_t bK   = (uint32_t)(((lane >> 3) & 1) * 8);

    // ---- prologue
    fillB(0, 0);
    fillA(0, 0);
    CP_COMMIT();

    for (int c = 0; c < NC; c++) {
        const int s = c & 1;
        if (c + 1 < NC) {
            fillB(c + 1, 1 - s);
            fillA(c + 1, 1 - s);
            CP_COMMIT();
            CP_WAIT1();
        } else {
            CP_WAIT0();
        }
        __syncthreads();

        const uint32_t baseAH = sb + OFF_AH(0) + (uint32_t)s * STG_SZ;
        const uint32_t baseAL = baseAH + 9216;
        const uint32_t baseBH = baseAH + 18432;
        const uint32_t baseBL = baseAH + 55296;

        #pragma unroll
        for (int kk = 0; kk < 4; kk++) {
            uint32_t ah[4][4], al[4][4], bh[8], bl[8];
            #pragma unroll
            for (int mt = 0; mt < 4; mt++) {
                const uint32_t ro = (uint32_t)((mt * 16 + aRow) * PITCHB + (kk * 16 + aK) * 2);
                ldsm4(ah[mt], baseAH + ro);
                ldsm4(al[mt], baseAL + ro);
            }
            #pragma unroll
            for (int j2 = 0; j2 < 2; j2++) {
                const uint32_t ro = (uint32_t)((nb + j2 * 16 + bRow) * PITCHB + (kk * 16 + bK) * 2);
                ldsm4(&bh[j2 * 4], baseBH + ro);
                ldsm4(&bl[j2 * 4], baseBL + ro);
            }
            #pragma unroll
            for (int mt = 0; mt < 4; mt++)
                #pragma unroll
                for (int nt = 0; nt < 4; nt++)
                    mma_bf16(acc[mt][nt], ah[mt], &bh[nt * 2]);
            #pragma unroll
            for (int mt = 0; mt < 4; mt++)
                #pragma unroll
                for (int nt = 0; nt < 4; nt++)
                    mma_bf16(acc[mt][nt], ah[mt], &bl[nt * 2]);
            #pragma unroll
            for (int mt = 0; mt < 4; mt++)
                #pragma unroll
                for (int nt = 0; nt < 4; nt++)
                    mma_bf16(acc[mt][nt], al[mt], &bh[nt * 2]);
        }
        __syncthreads();
    }

    // ---- epilogue: store fp32
    float* dst = (MODE == 0) ? (float*)g_y1 : dst_;
    #pragma unroll
    for (int mt = 0; mt < 4; mt++) {
        const int row = rowBase + mt * 16 + (lane >> 2);
        #pragma unroll
        for (int nt = 0; nt < 4; nt++) {
            const int col = nb + nt * 8 + 2 * (lane & 3);
            float2 v0 = {acc[mt][nt][0], acc[mt][nt][1]};
            float2 v1 = {acc[mt][nt][2], acc[mt][nt][3]};
            *(float2*)(dst + (size_t)row * HDIM + col)       = v0;
            *(float2*)(dst + (size_t)(row + 8) * HDIM + col) = v1;
        }
    }
}

// ---------------- 3) BN statistics (deterministic) --------------------------
template <int SRC>
__global__ void __launch_bounds__(256) stats_part_kernel(const float* __restrict__ ext) {
    const float* y = SRC ? ext : (const float*)g_y1;
    const int grp  = threadIdx.x & 63;   // 4-col group
    const int rsub = threadIdx.x >> 6;   // 0..3
    const size_t base = (size_t)blockIdx.x * 128;  // 128 rows per block
    float4 s = {0.f, 0.f, 0.f, 0.f}, q = {0.f, 0.f, 0.f, 0.f};
    #pragma unroll 4
    for (int k = 0; k < 32; k++) {
        const size_t row = base + rsub + 4 * k;
        float4 v = *(const float4*)(y + row * HDIM + grp * 4);
        s.x += v.x; s.y += v.y; s.z += v.z; s.w += v.w;
        q.x += v.x * v.x; q.y += v.y * v.y; q.z += v.z * v.z; q.w += v.w * v.w;
    }
    __shared__ float ss[4][256], sq[4][256];
    ss[rsub][grp * 4 + 0] = s.x; ss[rsub][grp * 4 + 1] = s.y;
    ss[rsub][grp * 4 + 2] = s.z; ss[rsub][grp * 4 + 3] = s.w;
    sq[rsub][grp * 4 + 0] = q.x; sq[rsub][grp * 4 + 1] = q.y;
    sq[rsub][grp * 4 + 2] = q.z; sq[rsub][grp * 4 + 3] = q.w;
    __syncthreads();
    const int ch = threadIdx.x;
    g_psum[blockIdx.x * HDIM + ch] = ((ss[0][ch] + ss[1][ch]) + (ss[2][ch] + ss[3][ch]));
    g_psq[blockIdx.x * HDIM + ch]  = ((sq[0][ch] + sq[1][ch]) + (sq[2][ch] + sq[3][ch]));
}

__global__ void __launch_bounds__(256) stats_final_kernel(const float* __restrict__ gamma,
                                                          const float* __restrict__ beta) {
    const int wid = threadIdx.x >> 5, lane = threadIdx.x & 31;
    const int ch = blockIdx.x * 8 + wid;
    float s = 0.f, q = 0.f;
    #pragma unroll 4
    for (int k = 0; k < NPART / 32; k++) {
        const int i = lane + 32 * k;
        s += g_psum[i * HDIM + ch];
        q += g_psq[i * HDIM + ch];
    }
    #pragma unroll
    for (int o = 16; o > 0; o >>= 1) {
        s += __shfl_xor_sync(0xffffffffu, s, o);
        q += __shfl_xor_sync(0xffffffffu, q, o);
    }
    if (lane == 0) {
        const float mean = s * (1.f / (float)ROWS);
        const float var  = q * (1.f / (float)ROWS) - mean * mean;
        const float a    = gamma[ch] * rsqrtf(var + 1e-5f);
        g_a[ch] = a;
        g_c[ch] = beta[ch] - mean * a;
    }
}

// ---------------- 4) in-place bn+relu on d_out ------------------------------
__global__ void __launch_bounds__(256) bnrelu_kernel(float* __restrict__ out) {
    size_t i = (size_t)blockIdx.x * 256 + threadIdx.x;   // float4 index
    float4* o4 = (float4*)out;
    float4 v = o4[i];
    int c = (int)((i << 2) & (HDIM - 1));
    v.x = fmaxf(v.x * g_a[c + 0] + g_c[c + 0], 0.f);
    v.y = fmaxf(v.y * g_a[c + 1] + g_c[c + 1], 0.f);
    v.z = fmaxf(v.z * g_a[c + 2] + g_c[c + 2], 0.f);
    v.w = fmaxf(v.w * g_a[c + 3] + g_c[c + 3], 0.f);
    o4[i] = v;
}

// ---------------- host ------------------------------------------------------
extern "C" void kernel_launch(void* const* d_in, const int* in_sizes, int n_in,
                              void* d_out, int out_size) {
    const float* xyz1    = (const float*)d_in[0];
    const float* xyz2    = (const float*)d_in[1];
    const float* points1 = (const float*)d_in[2];
    const float* points2 = (const float*)d_in[3];
    const float* W1      = (const float*)d_in[4];
    const float* b1      = (const float*)d_in[5];
    const float* gamma1  = (const float*)d_in[6];
    const float* beta1   = (const float*)d_in[7];
    const float* W2      = (const float*)d_in[8];
    const float* b2      = (const float*)d_in[9];
    const float* gamma2  = (const float*)d_in[10];
    const float* beta2   = (const float*)d_in[11];
    float* out = (float*)d_out;

    cudaFuncSetAttribute(gemm_hmma<0>, cudaFuncAttributeMaxDynamicSharedMemorySize, SMEM_SZ);
    cudaFuncSetAttribute(gemm_hmma<1>, cudaFuncAttributeMaxDynamicSharedMemorySize, SMEM_SZ);

    prep_w_kernel<<<(256 * 384) / 256, 256>>>(W1, W2);
    knn_kernel<<<BB * (NPTS / 256), 256>>>(xyz1, xyz2);

    gemm_hmma<0><<<ROWS / 64, 256, SMEM_SZ>>>(points1, points2, b1, nullptr);
    stats_part_kernel<0><<<NPART, 256>>>(nullptr);
    stats_final_kernel<<<HDIM / 8, 256>>>(gamma1, beta1);

    gemm_hmma<1><<<ROWS / 64, 256, SMEM_SZ>>>(nullptr, nullptr, b2, out);
    stats_part_kernel<1><<<NPART, 256>>>(out);
    stats_final_kernel<<<HDIM / 8, 256>>>(gamma2, beta2);

    bnrelu_kernel<<<(ROWS * HDIM / 4) / 256, 256>>>(out);
}

// round 4
// speedup vs baseline: 2.1082x; 1.0564x over previous
#include <cuda_runtime.h>
#include <cuda_bf16.h>
#include <cstdint>
#include <math.h>

// Problem constants (FP_Layer: B=8, N=8192, M=2048, C1=128, C2=256, H=256)
#define BB    8
#define NPTS  8192
#define MPTS  2048
#define C1    128
#define C2    256
#define HDIM  256
#define CIN   384
#define ROWS  (BB * NPTS)      // 65536
#define NPART 1024             // one partial per GEMM CTA (64 rows each)
#define KC    64               // K-chunk per stage (floats)

// ---------------- scratch (device globals; no allocation allowed) ----------
__device__ float g_y1[(size_t)ROWS * HDIM];     // 64 MB
__device__ int   g_idx[ROWS * 3];
__device__ float g_w[ROWS * 3];
__device__ float g_psum[NPART * HDIM];
__device__ float g_psq[NPART * HDIM];
__device__ float g_a[HDIM];
__device__ float g_c[HDIM];
// W pre-rounded to tf32, row-major [out_ch][in_ch]
__device__ __align__(16) float g_w1t[256 * 384];
__device__ __align__(16) float g_w2t[256 * 256];

// ================= PTX helpers (baseline ISA, OK on compute_103) ============
__device__ __forceinline__ uint32_t smem_u32(const void* p) {
    uint32_t a;
    asm("{ .reg .u64 t; cvta.to.shared.u64 t, %1; cvt.u32.u64 %0, t; }" : "=r"(a) : "l"(p));
    return a;
}
__device__ __forceinline__ void cpa16(uint32_t s, const void* g) {
    asm volatile("cp.async.cg.shared.global [%0], [%1], 16;" :: "r"(s), "l"(g));
}
#define CP_COMMIT() asm volatile("cp.async.commit_group;" ::: "memory")
#define CP_WAIT1()  asm volatile("cp.async.wait_group 1;" ::: "memory")
#define CP_WAIT0()  asm volatile("cp.async.wait_group 0;" ::: "memory")

__device__ __forceinline__ void ldsm4(uint32_t* r, uint32_t addr) {
    asm volatile("ldmatrix.sync.aligned.m8n8.x4.shared.b16 {%0,%1,%2,%3}, [%4];"
                 : "=r"(r[0]), "=r"(r[1]), "=r"(r[2]), "=r"(r[3]) : "r"(addr));
}
__device__ __forceinline__ void mma_tf32(float* c, const uint32_t* a, const uint32_t* b) {
    asm volatile(
        "mma.sync.aligned.m16n8k8.row.col.f32.tf32.tf32.f32 "
        "{%0,%1,%2,%3}, {%4,%5,%6,%7}, {%8,%9}, {%0,%1,%2,%3};"
        : "+f"(c[0]), "+f"(c[1]), "+f"(c[2]), "+f"(c[3])
        : "r"(a[0]), "r"(a[1]), "r"(a[2]), "r"(a[3]), "r"(b[0]), "r"(b[1]));
}
__device__ __forceinline__ uint32_t to_tf32(float v) {
    uint32_t o;
    asm("cvt.rna.tf32.f32 %0, %1;" : "=r"(o) : "f"(v));
    return o;
}

// ---------------- 0) round W to tf32 ----------------------------------------
__global__ void __launch_bounds__(256) prep_w_kernel(const float* __restrict__ W1,
                                                     const float* __restrict__ W2) {
    int i = blockIdx.x * 256 + threadIdx.x;   // grid covers 256*384
    g_w1t[i] = __uint_as_float(to_tf32(W1[i]));
    if (i < 256 * 256) g_w2t[i] = __uint_as_float(to_tf32(W2[i]));
}

// ---------------- 1) 3-NN over xyz2 for every xyz1 point -------------------
__global__ void __launch_bounds__(256) knn_kernel(const float* __restrict__ xyz1,
                                                  const float* __restrict__ xyz2) {
    __shared__ float4 s2[MPTS];               // x,y,z,|.|^2  (32KB)
    int b    = blockIdx.x >> 5;
    int tile = blockIdx.x & 31;
    const float* x2 = xyz2 + (size_t)b * MPTS * 3;
    for (int i = threadIdx.x; i < MPTS; i += 256) {
        float x = x2[i * 3 + 0], y = x2[i * 3 + 1], z = x2[i * 3 + 2];
        s2[i] = make_float4(x, y, z, x * x + y * y + z * z);
    }
    __syncthreads();

    int n = tile * 256 + threadIdx.x;
    int r = b * NPTS + n;
    float px = xyz1[(size_t)r * 3 + 0];
    float py = xyz1[(size_t)r * 3 + 1];
    float pz = xyz1[(size_t)r * 3 + 2];
    float pn = px * px + py * py + pz * pz;

    float d0 = 3.4e38f, d1 = 3.4e38f, d2 = 3.4e38f;
    int   i0 = 0, i1 = 0, i2 = 0;
    #pragma unroll 4
    for (int m = 0; m < MPTS; m++) {
        float4 t = s2[m];
        // identical formula to reference: |a|^2 + |b|^2 - 2 a.b
        float d = (pn + t.w) - 2.f * (px * t.x + py * t.y + pz * t.z);
        if (d < d2) {
            if (d < d1) {
                d2 = d1; i2 = i1;
                if (d < d0) { d1 = d0; i1 = i0; d0 = d; i0 = m; }
                else        { d1 = d;  i1 = m; }
            } else { d2 = d; i2 = m; }
        }
    }
    float r0 = 1.f / (d0 + 1e-8f);
    float r1 = 1.f / (d1 + 1e-8f);
    float r2 = 1.f / (d2 + 1e-8f);
    float s  = (r0 + r1) + r2;
    g_idx[r * 3 + 0] = i0; g_idx[r * 3 + 1] = i1; g_idx[r * 3 + 2] = i2;
    g_w[r * 3 + 0] = r0 / s; g_w[r * 3 + 1] = r1 / s; g_w[r * 3 + 2] = r2 / s;
}

// ---------------- 2) single-pass TF32 HMMA GEMM  C = A * W^T + bias ---------
// MODE 0: A = [points1 | interp(points2)] (K=384), writes g_y1
// MODE 1: A = relu(bn(g_y1))              (K=256), writes dst_
// CTA tile 64(M) x 256(N), 8 warps (warp tile 64x32), K-chunk 64, 2 stages.
// Epilogue also emits per-CTA BN partial sums (column sum / sumsq).
//
// smem: bias 1KB | bn_a 1KB | bn_c 1KB | 2 stages of { A 64x68 f32, B 256x68 f32 }
#define PITCH     68                       // floats per row (272B; 4-bank phase step)
#define OFF_BIAS  0
#define OFF_BNA   1024
#define OFF_BNC   2048
#define OFF_T     3072
#define A_SZ      (64 * PITCH * 4)         // 17408
#define B_SZ      (256 * PITCH * 4)        // 69632
#define STG_SZ    (A_SZ + B_SZ)            // 87040
#define OFF_A(s)  (OFF_T + (s) * STG_SZ)
#define OFF_B(s)  (OFF_A(s) + A_SZ)
#define SMEM_SZ   (OFF_T + 2 * STG_SZ)     // 177152

template <int MODE>
__global__ void __launch_bounds__(256, 1) gemm_tf32(const float* __restrict__ A0,
                                                    const float* __restrict__ P2,
                                                    const float* __restrict__ bias,
                                                    float* __restrict__ dst_) {
    constexpr int K  = MODE ? HDIM : CIN;
    constexpr int NC = K / KC;
    extern __shared__ char smem[];
    const uint32_t sb = smem_u32(smem);
    const int tid = threadIdx.x, wid = tid >> 5, lane = tid & 31;
    const int rowBase = blockIdx.x * 64;

    const float* WT = MODE ? g_w2t : g_w1t;

    float* sBias = (float*)(smem + OFF_BIAS);
    float* sBnA  = (float*)(smem + OFF_BNA);
    float* sBnC  = (float*)(smem + OFF_BNC);
    sBias[tid] = bias[tid];
    if (MODE == 1) { sBnA[tid] = g_a[tid]; sBnC[tid] = g_c[tid]; }
    __syncthreads();

    // ---- A-fill thread mapping: 4 threads per row, 16 k-floats each
    const int ar = tid >> 2;          // 0..63  (tile row)
    const int aq = tid & 3;           // 0..3   (k quarter)
    const int gr = rowBase + ar;      // global row

    int i0 = 0, i1 = 0, i2 = 0;
    float w0 = 0.f, w1 = 0.f, w2 = 0.f;
    const float* p2b = nullptr;
    if (MODE == 0) {
        i0 = g_idx[gr * 3 + 0]; i1 = g_idx[gr * 3 + 1]; i2 = g_idx[gr * 3 + 2];
        w0 = g_w[gr * 3 + 0];  w1 = g_w[gr * 3 + 1];  w2 = g_w[gr * 3 + 2];
        p2b = P2 + (size_t)(gr >> 13) * MPTS * C2;     // gr / NPTS
    }

    auto fillB = [&](int c, int s) {
        const int kt = c * KC;
        const uint32_t base = sb + OFF_B(s);
        #pragma unroll
        for (int it = 0; it < 16; it++) {
            const int idx = tid + 256 * it;        // 0..4095
            const int n = idx >> 4, j = idx & 15;  // W row, 16B chunk
            cpa16(base + (uint32_t)(n * (PITCH * 4) + j * 16),
                  WT + (size_t)n * K + kt + j * 4);
        }
    };
    auto fillA = [&](int c, int s) {
        const int kt = c * KC;
        const int kb = kt + aq * 16;
        float vals[16];
        if (MODE == 0) {
            if (kt < C1) {
                const float* src = A0 + (size_t)gr * C1 + kb;
                #pragma unroll
                for (int j = 0; j < 4; j++) {
                    float4 f = *(const float4*)(src + 4 * j);
                    vals[4 * j + 0] = f.x; vals[4 * j + 1] = f.y;
                    vals[4 * j + 2] = f.z; vals[4 * j + 3] = f.w;
                }
            } else {
                const int cc = kb - C1;
                const float* q0 = p2b + (size_t)i0 * C2 + cc;
                const float* q1 = p2b + (size_t)i1 * C2 + cc;
                const float* q2 = p2b + (size_t)i2 * C2 + cc;
                #pragma unroll
                for (int j = 0; j < 4; j++) {
                    float4 a = *(const float4*)(q0 + 4 * j);
                    float4 b = *(const float4*)(q1 + 4 * j);
                    float4 d = *(const float4*)(q2 + 4 * j);
                    vals[4 * j + 0] = a.x * w0 + b.x * w1 + d.x * w2;
                    vals[4 * j + 1] = a.y * w0 + b.y * w1 + d.y * w2;
                    vals[4 * j + 2] = a.z * w0 + b.z * w1 + d.z * w2;
                    vals[4 * j + 3] = a.w * w0 + b.w * w1 + d.w * w2;
                }
            }
        } else {
            const float* src = g_y1 + (size_t)gr * HDIM + kb;
            #pragma unroll
            for (int j = 0; j < 4; j++) {
                float4 f = *(const float4*)(src + 4 * j);
                const int g = kb + 4 * j;
                vals[4 * j + 0] = fmaxf(f.x * sBnA[g + 0] + sBnC[g + 0], 0.f);
                vals[4 * j + 1] = fmaxf(f.y * sBnA[g + 1] + sBnC[g + 1], 0.f);
                vals[4 * j + 2] = fmaxf(f.z * sBnA[g + 2] + sBnC[g + 2], 0.f);
                vals[4 * j + 3] = fmaxf(f.w * sBnA[g + 3] + sBnC[g + 3], 0.f);
            }
        }
        uint32_t* dst = (uint32_t*)(smem + OFF_A(s) + ar * (PITCH * 4) + aq * 64);
        #pragma unroll
        for (int j = 0; j < 4; j++) {
            uint4 t;
            t.x = to_tf32(vals[4 * j + 0]);
            t.y = to_tf32(vals[4 * j + 1]);
            t.z = to_tf32(vals[4 * j + 2]);
            t.w = to_tf32(vals[4 * j + 3]);
            *(uint4*)(dst + 4 * j) = t;
        }
    };

    // ---- accumulators init = bias (folded epilogue add)
    const int nb = wid * 32;
    float acc[4][4][4];
    #pragma unroll
    for (int nt = 0; nt < 4; nt++) {
        const float b0 = sBias[nb + nt * 8 + 2 * (lane & 3)];
        const float b1 = sBias[nb + nt * 8 + 2 * (lane & 3) + 1];
        #pragma unroll
        for (int mt = 0; mt < 4; mt++) {
            acc[mt][nt][0] = b0; acc[mt][nt][1] = b1;
            acc[mt][nt][2] = b0; acc[mt][nt][3] = b1;
        }
    }

    // ldmatrix per-lane address parts (tf32: 8x8 b16 tile == 8 rows x 4 tf32)
    const uint32_t lRow = (uint32_t)((lane & 7) + ((lane >> 3) & 1) * 8);
    const uint32_t lK   = (uint32_t)((lane >> 4) * 4);   // 0 or 4 tf32 cols

    // ---- prologue
    fillB(0, 0);
    fillA(0, 0);
    CP_COMMIT();

    for (int c = 0; c < NC; c++) {
        const int s = c & 1;
        if (c + 1 < NC) {
            fillB(c + 1, 1 - s);
            fillA(c + 1, 1 - s);
            CP_COMMIT();
            CP_WAIT1();
        } else {
            CP_WAIT0();
        }
        __syncthreads();

        const uint32_t baseA = sb + OFF_A(0) + (uint32_t)s * STG_SZ;
        const uint32_t baseB = baseA + A_SZ;

        #pragma unroll
        for (int kk = 0; kk < 8; kk++) {
            const uint32_t kcol = (uint32_t)(kk * 8) + lK;
            uint32_t a[4][4], bq[2][4];
            #pragma unroll
            for (int mt = 0; mt < 4; mt++)
                ldsm4(a[mt], baseA + ((mt * 16 + lRow) * PITCH + kcol) * 4);
            #pragma unroll
            for (int p = 0; p < 2; p++)
                ldsm4(bq[p], baseB + ((nb + p * 16 + lRow) * PITCH + kcol) * 4);
            #pragma unroll
            for (int mt = 0; mt < 4; mt++) {
                #pragma unroll
                for (int nt = 0; nt < 4; nt++) {
                    uint32_t bfrag[2] = { bq[nt >> 1][nt & 1], bq[nt >> 1][(nt & 1) + 2] };
                    mma_tf32(acc[mt][nt], a[mt], bfrag);
                }
            }
        }
        __syncthreads();
    }

    // ---- epilogue 1: per-CTA BN partials from accumulators
    {
        #pragma unroll
        for (int nt = 0; nt < 4; nt++) {
            float s0 = 0.f, s1 = 0.f, q0 = 0.f, q1 = 0.f;
            #pragma unroll
            for (int mt = 0; mt < 4; mt++) {
                float v0 = acc[mt][nt][0], v1 = acc[mt][nt][1];
                float v2 = acc[mt][nt][2], v3 = acc[mt][nt][3];
                s0 += v0 + v2;  s1 += v1 + v3;
                q0 += v0 * v0 + v2 * v2;  q1 += v1 * v1 + v3 * v3;
            }
            #pragma unroll
            for (int o = 4; o < 32; o <<= 1) {
                s0 += __shfl_xor_sync(0xffffffffu, s0, o);
                s1 += __shfl_xor_sync(0xffffffffu, s1, o);
                q0 += __shfl_xor_sync(0xffffffffu, q0, o);
                q1 += __shfl_xor_sync(0xffffffffu, q1, o);
            }
            if (lane < 4) {
                const int col = nb + nt * 8 + 2 * lane;
                g_psum[blockIdx.x * HDIM + col]     = s0;
                g_psum[blockIdx.x * HDIM + col + 1] = s1;
                g_psq[blockIdx.x * HDIM + col]      = q0;
                g_psq[blockIdx.x * HDIM + col + 1]  = q1;
            }
        }
    }

    // ---- epilogue 2: store fp32 y
    float* dst = (MODE == 0) ? (float*)g_y1 : dst_;
    #pragma unroll
    for (int mt = 0; mt < 4; mt++) {
        const int row = rowBase + mt * 16 + (lane >> 2);
        #pragma unroll
        for (int nt = 0; nt < 4; nt++) {
            const int col = nb + nt * 8 + 2 * (lane & 3);
            float2 v0 = {acc[mt][nt][0], acc[mt][nt][1]};
            float2 v1 = {acc[mt][nt][2], acc[mt][nt][3]};
            *(float2*)(dst + (size_t)row * HDIM + col)       = v0;
            *(float2*)(dst + (size_t)(row + 8) * HDIM + col) = v1;
        }
    }
}

// ---------------- 3) BN stats final reduce ----------------------------------
__global__ void __launch_bounds__(256) stats_final_kernel(const float* __restrict__ gamma,
                                                          const float* __restrict__ beta) {
    const int wid = threadIdx.x >> 5, lane = threadIdx.x & 31;
    const int ch = blockIdx.x * 8 + wid;
    float s = 0.f, q = 0.f;
    #pragma unroll 4
    for (int k = 0; k < NPART / 32; k++) {
        const int i = lane + 32 * k;
        s += g_psum[i * HDIM + ch];
        q += g_psq[i * HDIM + ch];
    }
    #pragma unroll
    for (int o = 16; o > 0; o >>= 1) {
        s += __shfl_xor_sync(0xffffffffu, s, o);
        q += __shfl_xor_sync(0xffffffffu, q, o);
    }
    if (lane == 0) {
        const float mean = s * (1.f / (float)ROWS);
        const float var  = q * (1.f / (float)ROWS) - mean * mean;
        const float a    = gamma[ch] * rsqrtf(var + 1e-5f);
        g_a[ch] = a;
        g_c[ch] = beta[ch] - mean * a;
    }
}

// ---------------- 4) in-place bn+relu on d_out ------------------------------
__global__ void __launch_bounds__(256) bnrelu_kernel(float* __restrict__ out) {
    size_t i = (size_t)blockIdx.x * 256 + threadIdx.x;   // float4 index
    float4* o4 = (float4*)out;
    float4 v = o4[i];
    int c = (int)((i << 2) & (HDIM - 1));
    v.x = fmaxf(v.x * g_a[c + 0] + g_c[c + 0], 0.f);
    v.y = fmaxf(v.y * g_a[c + 1] + g_c[c + 1], 0.f);
    v.z = fmaxf(v.z * g_a[c + 2] + g_c[c + 2], 0.f);
    v.w = fmaxf(v.w * g_a[c + 3] + g_c[c + 3], 0.f);
    o4[i] = v;
}

// ---------------- host ------------------------------------------------------
extern "C" void kernel_launch(void* const* d_in, const int* in_sizes, int n_in,
                              void* d_out, int out_size) {
    const float* xyz1    = (const float*)d_in[0];
    const float* xyz2    = (const float*)d_in[1];
    const float* points1 = (const float*)d_in[2];
    const float* points2 = (const float*)d_in[3];
    const float* W1      = (const float*)d_in[4];
    const float* b1      = (const float*)d_in[5];
    const float* gamma1  = (const float*)d_in[6];
    const float* beta1   = (const float*)d_in[7];
    const float* W2      = (const float*)d_in[8];
    const float* b2      = (const float*)d_in[9];
    const float* gamma2  = (const float*)d_in[10];
    const float* beta2   = (const float*)d_in[11];
    float* out = (float*)d_out;

    cudaFuncSetAttribute(gemm_tf32<0>, cudaFuncAttributeMaxDynamicSharedMemorySize, SMEM_SZ);
    cudaFuncSetAttribute(gemm_tf32<1>, cudaFuncAttributeMaxDynamicSharedMemorySize, SMEM_SZ);

    prep_w_kernel<<<(256 * 384) / 256, 256>>>(W1, W2);
    knn_kernel<<<BB * (NPTS / 256), 256>>>(xyz1, xyz2);

    gemm_tf32<0><<<ROWS / 64, 256, SMEM_SZ>>>(points1, points2, b1, nullptr);
    stats_final_kernel<<<HDIM / 8, 256>>>(gamma1, beta1);

    gemm_tf32<1><<<ROWS / 64, 256, SMEM_SZ>>>(nullptr, nullptr, b2, out);
    stats_final_kernel<<<HDIM / 8, 256>>>(gamma2, beta2);

    bnrelu_kernel<<<(ROWS * HDIM / 4) / 256, 256>>>(out);
}